// round 4
// baseline (speedup 1.0000x reference)
#include <cuda_runtime.h>

// Rz_layer, fused single kernel with 4-way batch amortization.
//   out = exp(-0.5i * phase(blk, d)) * (re + i*im)
//   phase(blk, d) = sum_q w[blk][q] * (1 - 2*bit_q(d))
//   E(d) = exp(-i*phase/2) = E_hi[d>>6] * E_lo[d&63]
//   out_re = E.re*r - E.im*m ; out_im = E.re*m + E.im*r
//
// Shapes: state (256, 32, 2, 4096) fp32; weights (32, 12) fp32.
// Output: (2, 256, 32, 2, 4096) fp32 -> real plane then imag plane.
//
// float4-index bit layout: [batch(8):16 | blk(5):11 | dc(1):10 | d4(10):0].
// Each CTA handles 4 segments spaced GRID*256 = 1<<22 apart — a pure batch-bit
// stride, so (blk, d-range) and therefore the whole factor table are invariant
// across segments: 80 sincos built once in smem, reused 4x.

#define NQ       12
#define DIM      4096
#define NBLOCKS  32
#define DC       2
#define BATCH    256
#define NELEM    (BATCH * NBLOCKS * DC * DIM)   // 67108864
#define SEGS     4
#define GRID     (NELEM / 4 / 256 / SEGS)       // 16384
#define SEG_STRIDE (GRID * 256)                 // 1<<22 float4

__device__ __forceinline__ float2 cmul(float2 a, float2 b) {
    float2 r;
    r.x = fmaf(a.x, b.x, -a.y * b.y);
    r.y = fmaf(a.x, b.y,  a.y * b.x);
    return r;
}

__global__ void __launch_bounds__(256)
rz_fused_kernel(const float*  __restrict__ w,
                const float4* __restrict__ re,
                const float4* __restrict__ im,
                float4*       __restrict__ out_re,
                float4*       __restrict__ out_im) {
    __shared__ float2 s_hi[16];   // E_hi for this CTA's 16 (d>>6) values
    __shared__ float2 s_lo[64];   // E_lo for all 64 (d&63) values

    const int tid    = threadIdx.x;
    const int u_base = blockIdx.x << 8;          // first float4 index of CTA

    const int blk     = (u_base >> 11) & 31;     // invariant across segments
    const int hi_base = (u_base & 1023) >> 4;    // 0/16/32/48

    // ---- build per-CTA factor tables (80 sincos, once) ----
    if (tid < 16) {
        int j = hi_base + tid;                   // the d>>6 value
        float angle = 0.0f;
#pragma unroll
        for (int q = 0; q < 6; q++) {
            float sign = ((j >> (5 - q)) & 1) ? -0.5f : 0.5f;
            angle = fmaf(__ldg(&w[blk * NQ + q]), sign, angle);
        }
        float s, c;
        sincosf(angle, &s, &c);
        s_hi[tid] = make_float2(c, -s);          // exp(-i*angle)
    } else if (tid >= 64 && tid < 128) {
        int j = tid - 64;                        // the d&63 value
        float angle = 0.0f;
#pragma unroll
        for (int q = 0; q < 6; q++) {
            float sign = ((j >> (5 - q)) & 1) ? -0.5f : 0.5f;
            angle = fmaf(__ldg(&w[blk * NQ + 6 + q]), sign, angle);
        }
        float s, c;
        sincosf(angle, &s, &c);
        s_lo[j] = make_float2(c, -s);
    }
    __syncthreads();

    // ---- per-thread rotation coefficients (invariant across segments) ----
    float2 eh = s_hi[tid >> 4];
    const float4* lo4 = reinterpret_cast<const float4*>(s_lo);
    int lb = (tid & 15) << 1;
    float4 lo01 = lo4[lb];
    float4 lo23 = lo4[lb + 1];

    float2 E0 = cmul(eh, make_float2(lo01.x, lo01.y));
    float2 E1 = cmul(eh, make_float2(lo01.z, lo01.w));
    float2 E2 = cmul(eh, make_float2(lo23.x, lo23.y));
    float2 E3 = cmul(eh, make_float2(lo23.z, lo23.w));

    // ---- streaming complex rotation over 4 batch segments ----
    int u = u_base + tid;
#pragma unroll
    for (int s = 0; s < SEGS; s++, u += SEG_STRIDE) {
        float4 r = __ldcs(&re[u]);               // streaming, evict-first
        float4 m = __ldcs(&im[u]);

        float4 orr, oii;
        orr.x = fmaf(E0.x, r.x, -E0.y * m.x);
        oii.x = fmaf(E0.x, m.x,  E0.y * r.x);
        orr.y = fmaf(E1.x, r.y, -E1.y * m.y);
        oii.y = fmaf(E1.x, m.y,  E1.y * r.y);
        orr.z = fmaf(E2.x, r.z, -E2.y * m.z);
        oii.z = fmaf(E2.x, m.z,  E2.y * r.z);
        orr.w = fmaf(E3.x, r.w, -E3.y * m.w);
        oii.w = fmaf(E3.x, m.w,  E3.y * r.w);

        __stcs(&out_re[u], orr);
        __stcs(&out_im[u], oii);
    }
}

extern "C" void kernel_launch(void* const* d_in, const int* in_sizes, int n_in,
                              void* d_out, int out_size) {
    // metadata order: state_re, state_im, weights — robust to the small
    // (384-element) weights tensor landing in any slot.
    const float* sre = nullptr;
    const float* sim = nullptr;
    const float* w   = nullptr;
    for (int i = 0; i < n_in; i++) {
        if (in_sizes[i] == NBLOCKS * NQ) { w = (const float*)d_in[i]; }
        else if (!sre)                   { sre = (const float*)d_in[i]; }
        else                             { sim = (const float*)d_in[i]; }
    }

    float* out = (float*)d_out;        // [0, NELEM) real, [NELEM, 2*NELEM) imag

    rz_fused_kernel<<<GRID, 256>>>(w,
                                   (const float4*)sre,
                                   (const float4*)sim,
                                   (float4*)out,
                                   (float4*)(out + NELEM));
}

// round 5
// speedup vs baseline: 1.0199x; 1.0199x over previous
#include <cuda_runtime.h>

// Rz_layer, fused single kernel, loads-first ordering.
//   out = exp(-0.5i * phase(blk, d)) * (re + i*im)
//   phase(blk, d) = sum_q w[blk][q] * (1 - 2*bit_q(d))
//   E(d) = exp(-i*phase/2) = E_hi[d>>6] * E_lo[d&63]
//   out_re = E.re*r - E.im*m ; out_im = E.re*m + E.im*r
//
// Shapes: state (256, 32, 2, 4096) fp32; weights (32, 12) fp32.
// Output: (2, 256, 32, 2, 4096) fp32 -> real plane then imag plane.
//
// Key ordering: every thread issues its two global state loads BEFORE the
// smem factor-table build + barrier, so the ~300cyc sincos chain and the BAR
// drain inside the ~600cyc DRAM-load shadow instead of serializing ahead of it.

#define NQ       12
#define DIM      4096
#define NBLOCKS  32
#define DC       2
#define BATCH    256
#define NELEM    (BATCH * NBLOCKS * DC * DIM)   // 67108864

__device__ __forceinline__ float2 cmul(float2 a, float2 b) {
    float2 r;
    r.x = fmaf(a.x, b.x, -a.y * b.y);
    r.y = fmaf(a.x, b.y,  a.y * b.x);
    return r;
}

__global__ void __launch_bounds__(256)
rz_fused_kernel(const float*  __restrict__ w,
                const float4* __restrict__ re,
                const float4* __restrict__ im,
                float4*       __restrict__ out_re,
                float4*       __restrict__ out_im) {
    __shared__ float2 s_hi[16];   // E_hi for this CTA's 16 (d>>6) values
    __shared__ float2 s_lo[64];   // E_lo for all 64 (d&63) values

    const int tid    = threadIdx.x;
    const int u_base = blockIdx.x << 8;          // first float4 index of CTA
    const int u      = u_base + tid;

    // ---- issue state loads FIRST (latency starts now) ----
    float4 r = __ldcs(&re[u]);                   // streaming, evict-first
    float4 m = __ldcs(&im[u]);

    const int blk     = (u_base >> 11) & 31;     // same for whole CTA
    const int hi_base = (u_base & 1023) >> 4;    // 0/16/32/48

    // ---- build per-CTA factor tables (80 sincos) under the load shadow ----
    if (tid < 16) {
        int j = hi_base + tid;                   // the d>>6 value
        float angle = 0.0f;
#pragma unroll
        for (int q = 0; q < 6; q++) {
            float sign = ((j >> (5 - q)) & 1) ? -0.5f : 0.5f;
            angle = fmaf(__ldg(&w[blk * NQ + q]), sign, angle);
        }
        float s, c;
        sincosf(angle, &s, &c);
        s_hi[tid] = make_float2(c, -s);          // exp(-i*angle)
    } else if (tid >= 64 && tid < 128) {
        int j = tid - 64;                        // the d&63 value
        float angle = 0.0f;
#pragma unroll
        for (int q = 0; q < 6; q++) {
            float sign = ((j >> (5 - q)) & 1) ? -0.5f : 0.5f;
            angle = fmaf(__ldg(&w[blk * NQ + 6 + q]), sign, angle);
        }
        float s, c;
        sincosf(angle, &s, &c);
        s_lo[j] = make_float2(c, -s);
    }
    __syncthreads();

    // ---- per-thread rotation coefficients from smem ----
    // d = 4*u; d>>6 = hi_base + (tid>>4); d&63 = (tid&15)*4 + 0..3
    float2 eh = s_hi[tid >> 4];
    const float4* lo4 = reinterpret_cast<const float4*>(s_lo);
    int lb = (tid & 15) << 1;
    float4 lo01 = lo4[lb];
    float4 lo23 = lo4[lb + 1];

    float2 E0 = cmul(eh, make_float2(lo01.x, lo01.y));
    float2 E1 = cmul(eh, make_float2(lo01.z, lo01.w));
    float2 E2 = cmul(eh, make_float2(lo23.x, lo23.y));
    float2 E3 = cmul(eh, make_float2(lo23.z, lo23.w));

    float4 orr, oii;
    orr.x = fmaf(E0.x, r.x, -E0.y * m.x);
    oii.x = fmaf(E0.x, m.x,  E0.y * r.x);
    orr.y = fmaf(E1.x, r.y, -E1.y * m.y);
    oii.y = fmaf(E1.x, m.y,  E1.y * r.y);
    orr.z = fmaf(E2.x, r.z, -E2.y * m.z);
    oii.z = fmaf(E2.x, m.z,  E2.y * r.z);
    orr.w = fmaf(E3.x, r.w, -E3.y * m.w);
    oii.w = fmaf(E3.x, m.w,  E3.y * r.w);

    __stcs(&out_re[u], orr);
    __stcs(&out_im[u], oii);
}

extern "C" void kernel_launch(void* const* d_in, const int* in_sizes, int n_in,
                              void* d_out, int out_size) {
    // metadata order: state_re, state_im, weights — robust to the small
    // (384-element) weights tensor landing in any slot.
    const float* sre = nullptr;
    const float* sim = nullptr;
    const float* w   = nullptr;
    for (int i = 0; i < n_in; i++) {
        if (in_sizes[i] == NBLOCKS * NQ) { w = (const float*)d_in[i]; }
        else if (!sre)                   { sre = (const float*)d_in[i]; }
        else                             { sim = (const float*)d_in[i]; }
    }

    float* out = (float*)d_out;        // [0, NELEM) real, [NELEM, 2*NELEM) imag

    const int n4 = NELEM / 4;          // 16777216
    rz_fused_kernel<<<n4 / 256, 256>>>(w,
                                       (const float4*)sre,
                                       (const float4*)sim,
                                       (float4*)out,
                                       (float4*)(out + NELEM));
}